// round 14
// baseline (speedup 1.0000x reference)
#include <cuda_runtime.h>
#include <cuda_fp16.h>
#include <cstdint>

// Problem constants
#define B_   8
#define H_   8
#define S_   4096
#define D_   64
#define DM_  768
#define SM2  (S_ - 2)            // 4094 (rows entering the Hebbian update)
#define RPB  (S_ - 1)            // 4095 (rows per batch incl. A-only row i=4094)
#define ROWS_A (B_ * RPB)        // 32760
#define DENOM ((float)(B_ * SM2))

#define GCH   32                 // gram chunks
#define GROWS 1024               // rows per chunk

#define MROWS (B_ * S_)          // 32768
#define KDIM  (H_ * D_)          // 512

// ---------------------------------------------------------------------------
// Static device scratch (allocation-free per harness rules)
// ---------------------------------------------------------------------------
__device__ float g_scratch[H_][GCH][2][D_ * D_];
__device__ float g_NT[H_][D_ * D_];
__device__ __align__(16) __half g_Ahi[(size_t)MROWS * KDIM];
__device__ __align__(16) __half g_Bhi[(size_t)DM_ * KDIM];

// ---------------------------------------------------------------------------
// Helpers
// ---------------------------------------------------------------------------
__device__ __forceinline__ uint32_t smem_to_u32(const void* p) {
    uint32_t a;
    asm("{ .reg .u64 t; cvta.to.shared.u64 t, %1; cvt.u32.u64 %0, t; }" : "=r"(a) : "l"(p));
    return a;
}
__device__ __forceinline__ void mma_16816_f16(float* c, const uint32_t* a, const uint32_t* b) {
    asm volatile(
        "mma.sync.aligned.m16n8k16.row.col.f32.f16.f16.f32 "
        "{%0,%1,%2,%3}, {%4,%5,%6,%7}, {%8,%9}, {%0,%1,%2,%3};"
        : "+f"(c[0]), "+f"(c[1]), "+f"(c[2]), "+f"(c[3])
        : "r"(a[0]), "r"(a[1]), "r"(a[2]), "r"(a[3]), "r"(b[0]), "r"(b[1]));
}
__device__ __forceinline__ void ldsm_x4_trans(uint32_t& r0, uint32_t& r1,
                                              uint32_t& r2, uint32_t& r3, uint32_t addr) {
    asm volatile("ldmatrix.sync.aligned.m8n8.x4.trans.shared.b16 {%0,%1,%2,%3}, [%4];"
                 : "=r"(r0), "=r"(r1), "=r"(r2), "=r"(r3) : "r"(addr));
}
#define CP_ASYNC_16(smem_u32, gptr) \
    asm volatile("cp.async.cg.shared.global [%0], [%1], 16;" :: "r"(smem_u32), "l"(gptr))
#define CP_ASYNC_COMMIT() asm volatile("cp.async.commit_group;")
#define CP_ASYNC_WAIT(n)  asm volatile("cp.async.wait_group %0;" :: "n"(n))

// ---------------------------------------------------------------------------
// Kernel 1 (fused): per-(head, chunk) Gram partials via tensor cores, the
// fp16 Qaddr A-matrix write, AND the s=0 zero rows (zeroA merged, c==0 only).
// ---------------------------------------------------------------------------
#define RT 64       // rows per stage
#define RP 72       // padded halfs per smem row

__global__ __launch_bounds__(256, 2) void gram_mma(const float* __restrict__ Q,
                                                   const float* __restrict__ V) {
    const int c = blockIdx.x;   // chunk (1024 rows)
    const int h = blockIdx.y;
    const int t = threadIdx.x;
    const int wid = t >> 5, lane = t & 31;

    // zeroA fusion: block (0,h) zeroes A row b*4096 cols h*64..h*64+63, all b.
    if (c == 0 && t < 64) {
        const int b = t >> 3;       // 0..7
        const int g = t & 7;        // 8-half group
        __half zz[8];
#pragma unroll
        for (int j = 0; j < 8; ++j) zz[j] = __float2half(0.f);
        *(uint4*)(g_Ahi + (((size_t)b * S_) << 9) + h * 64 + g * 8) = *(uint4*)zz;
    }

    __shared__ __half Tqh[RT * RP];   // q_hat, k-major: [r][d]
    __shared__ __half Tq [RT * RP];   // q
    __shared__ __half Tv [RT * RP];   // v (shift+2)

    const uint32_t sTqh = smem_to_u32(Tqh);
    const uint32_t sTq  = smem_to_u32(Tq);
    const uint32_t sTv  = smem_to_u32(Tv);

    const int lr = t >> 2;
    const int tq = t & 3;

    const int p0 = 16 * (wid & 3);
    const uint32_t TA = (wid < 4) ? sTqh : sTq;
    const uint32_t TB = (wid < 4) ? sTqh : sTv;
    const int l8  = lane & 7;
    const int sub = lane >> 3;
    const uint32_t a_off = (uint32_t)((((sub >> 1) * 8 + l8) * RP + p0 + (sub & 1) * 8) * 2);
    const uint32_t b_off = (uint32_t)((((sub & 1) * 8 + l8) * RP + (sub >> 1) * 8) * 2);

    float acc[8][4];
#pragma unroll
    for (int i = 0; i < 8; ++i)
#pragma unroll
        for (int j = 0; j < 4; ++j) acc[i][j] = 0.f;

    for (int st = 0; st < GROWS / RT; ++st) {            // 16 stages
        const int gr = c * GROWS + st * RT + lr;
        float q[16], v[16];
#pragma unroll
        for (int i = 0; i < 16; ++i) { q[i] = 0.f; v[i] = 0.f; }
        const bool valid = (gr < ROWS_A);
        int b = 0, i = 0;
        if (valid) {
            b = gr / RPB;
            i = gr - b * RPB;                            // 0..4094
            const float* qrow = Q + (((size_t)(b * H_ + h)) * S_ + i) * D_ + tq * 16;
#pragma unroll
            for (int j = 0; j < 4; ++j)
                *(float4*)&q[j * 4] = *(const float4*)(qrow + j * 4);
            if (i < SM2) {
                const float* vrow = V + (((size_t)(b * H_ + h)) * S_ + i + 2) * D_ + tq * 16;
#pragma unroll
                for (int j = 0; j < 4; ++j)
                    *(float4*)&v[j * 4] = *(const float4*)(vrow + j * 4);
            }
        }
        // fp16 of raw q — doubles as the A-matrix payload (prepA fusion)
        __half2 hq[8];
#pragma unroll
        for (int j = 0; j < 8; ++j) hq[j] = __floats2half2_rn(q[2 * j], q[2 * j + 1]);
        if (valid) {
            __half* d = g_Ahi + (((size_t)(b * S_ + i + 1)) << 9) + h * 64 + tq * 16;
            *(uint4*)(d)     = *(uint4*)&hq[0];
            *(uint4*)(d + 8) = *(uint4*)&hq[4];
        }
        // mask A-only row (i == 4094) and out-of-range rows out of the MMA
        const bool active = valid && (i < SM2);
        if (!active) {
#pragma unroll
            for (int j = 0; j < 16; ++j) q[j] = 0.f;
#pragma unroll
            for (int j = 0; j < 8; ++j) hq[j] = __halves2half2(__half(0), __half(0));
        }
        // row norm across the 4 lanes covering this row
        float ss = 0.f;
#pragma unroll
        for (int j = 0; j < 16; ++j) ss += q[j] * q[j];
        ss += __shfl_xor_sync(0xffffffffu, ss, 1);
        ss += __shfl_xor_sync(0xffffffffu, ss, 2);
        const float inv = 1.0f / fmaxf(sqrtf(ss), 1e-8f);

        __half2 hqh[8], hv[8];
#pragma unroll
        for (int j = 0; j < 8; ++j) {
            hqh[j] = __floats2half2_rn(q[2 * j] * inv, q[2 * j + 1] * inv);
            hv[j]  = __floats2half2_rn(v[2 * j], v[2 * j + 1]);
        }
        __syncthreads();   // previous stage's mma reads done
        {
            __half* d0 = Tqh + lr * RP + tq * 16;
            *(uint4*)(d0)     = *(uint4*)&hqh[0];
            *(uint4*)(d0 + 8) = *(uint4*)&hqh[4];
            __half* d1 = Tq + lr * RP + tq * 16;
            *(uint4*)(d1)     = *(uint4*)&hq[0];
            *(uint4*)(d1 + 8) = *(uint4*)&hq[4];
            __half* d2 = Tv + lr * RP + tq * 16;
            *(uint4*)(d2)     = *(uint4*)&hv[0];
            *(uint4*)(d2 + 8) = *(uint4*)&hv[4];
        }
        __syncthreads();

#pragma unroll
        for (int ks = 0; ks < RT / 16; ++ks) {           // 4 k16-steps
            const uint32_t kb = (uint32_t)(ks * 16 * RP * 2);
            uint32_t a[4];
            ldsm_x4_trans(a[0], a[1], a[2], a[3], TA + kb + a_off);
#pragma unroll
            for (int nt = 0; nt < 8; nt += 2) {
                uint32_t b0, b1, b2, b3;
                ldsm_x4_trans(b0, b1, b2, b3, TB + kb + b_off + nt * 8 * 2);
                uint32_t bb0[2] = {b0, b1};
                uint32_t bb1[2] = {b2, b3};
                mma_16816_f16(acc[nt],     a, bb0);
                mma_16816_f16(acc[nt + 1], a, bb1);
            }
        }
    }

    // write partials
    float* o = g_scratch[h][c][(wid < 4) ? 0 : 1];
    const int fr = lane >> 2;
    const int c2 = (lane & 3) * 2;
#pragma unroll
    for (int nt = 0; nt < 8; ++nt) {
        const int col = nt * 8 + c2;
        *(float2*)&o[(p0 + fr) * 64 + col]     = make_float2(acc[nt][0], acc[nt][1]);
        *(float2*)&o[(p0 + fr + 8) * 64 + col] = make_float2(acc[nt][2], acc[nt][3]);
    }
}

// ---------------------------------------------------------------------------
// Kernel 2 (fused reduce + combine) — EXACT R13.
// ---------------------------------------------------------------------------
__global__ __launch_bounds__(256) void reduce_combine(const float* __restrict__ trace) {
    const int h  = blockIdx.y;
    const int p0 = blockIdx.x * 8;
    const int t  = threadIdx.x;

    __shared__ float Ts[4096];
    __shared__ float Gs[8 * 64];
    __shared__ float Us[8 * 64];

#pragma unroll
    for (int j = 0; j < 16; ++j)
        Ts[t + 256 * j] = trace[h * 4096 + t + 256 * j];

#pragma unroll
    for (int j = 0; j < 2; ++j) {
        const int e   = t + 256 * j;
        const int idx = p0 * 64 + e;
        float sg = 0.f, su = 0.f;
#pragma unroll 4
        for (int c = 0; c < GCH; ++c) {
            sg += g_scratch[h][c][0][idx];
            su += g_scratch[h][c][1][idx];
        }
        Gs[e] = sg;
        Us[e] = su;
    }
    __syncthreads();

    const float invd = 1.0f / DENOM;
#pragma unroll
    for (int j = 0; j < 2; ++j) {
        const int e  = t + 256 * j;
        const int pl = e >> 6, q = e & 63;
        float acc = 0.f;
#pragma unroll 8
        for (int k = 0; k < 64; ++k)
            acc += Gs[pl * 64 + k] * Ts[k * 64 + q];
        g_NT[h][(p0 + pl) * 64 + q] =
            0.99f * (Ts[(p0 + pl) * 64 + q] - acc * invd) + 0.1f * Us[e] * invd;
    }
}

// ---------------------------------------------------------------------------
// Kernel 3: B[n][h*64+p] = sum_q NT[h][p][q] * W[n][h*64+q] -> fp16. EXACT R13.
// ---------------------------------------------------------------------------
__global__ __launch_bounds__(256) void build_M(const float* __restrict__ W) {
    const int h  = blockIdx.y;
    const int n0 = blockIdx.x * 64;
    const int t  = threadIdx.x;
    __shared__ float Wq[64][72];   // [q][n]
    __shared__ float Nq[64][72];   // [q][p]
#pragma unroll
    for (int j = 0; j < 4; ++j) {
        const int idx = t + j * 256;
        const int row = idx >> 4;
        const int q4  = (idx & 15) * 4;
        float4 wv = *(const float4*)(W + (size_t)(n0 + row) * KDIM + h * 64 + q4);
        Wq[q4 + 0][row] = wv.x; Wq[q4 + 1][row] = wv.y;
        Wq[q4 + 2][row] = wv.z; Wq[q4 + 3][row] = wv.w;
        float4 nv = *(const float4*)(&g_NT[h][row * 64 + q4]);
        Nq[q4 + 0][row] = nv.x; Nq[q4 + 1][row] = nv.y;
        Nq[q4 + 2][row] = nv.z; Nq[q4 + 3][row] = nv.w;
    }
    __syncthreads();
    const int tx = t & 15;     // p block
    const int ty = t >> 4;     // n block
    float acc[4][4];
#pragma unroll
    for (int i = 0; i < 4; ++i)
#pragma unroll
        for (int j = 0; j < 4; ++j) acc[i][j] = 0.f;
#pragma unroll 8
    for (int q = 0; q < 64; ++q) {
        const float4 wv = *(const float4*)&Wq[q][ty * 4];
        const float4 nv = *(const float4*)&Nq[q][tx * 4];
        const float w[4] = {wv.x, wv.y, wv.z, wv.w};
        const float nn[4] = {nv.x, nv.y, nv.z, nv.w};
#pragma unroll
        for (int i = 0; i < 4; ++i)
#pragma unroll
            for (int j = 0; j < 4; ++j)
                acc[i][j] += w[i] * nn[j];
    }
#pragma unroll
    for (int i = 0; i < 4; ++i) {
        const int n = n0 + ty * 4 + i;
#pragma unroll
        for (int j = 0; j < 4; ++j) {
            const int k = h * 64 + tx * 4 + j;
            g_Bhi[(size_t)n * KDIM + k] = __float2half_rn(acc[i][j]);
        }
    }
}

// ---------------------------------------------------------------------------
// Kernel 4: out = Ahi @ Bhi^T — persistent 296-CTA version with cross-tile
// cp.async pipelining. Per-tile math identical to R13 (bit-identical output).
// Tiles m-major: tile -> n = tile>>8, m = tile&255.
// ---------------------------------------------------------------------------
#define STG_BYTES 36864                         // (128*72 + 128*72) * 2B
#define GEMM_SMEM (2 * STG_BYTES)               // 73728
#define NTILES (6 * 256)                        // 1536
#define GEMM_GRID 296

__global__ __launch_bounds__(256, 2) void out_gemm_mma(float* __restrict__ out) {
    extern __shared__ __align__(16) char smem[];
    const int t = threadIdx.x;
    const uint32_t sbase = smem_to_u32(smem);

    const int lrow = t >> 3;
    const int lc8  = t & 7;

    // load chunk kc of tile (m_base, n_base) into stage buffer `buf`
    auto load_stage = [&](int m_base, int n_base, int kc, int buf) {
        const int k0 = kc * 64;
        const uint32_t sa = sbase + buf * STG_BYTES;
        const uint32_t sb = sa + 128 * 144;
#pragma unroll
        for (int i = 0; i < 4; ++i) {
            const int row = lrow + i * 32;
            const __half* g = g_Ahi + (((size_t)(m_base + row)) << 9) + k0 + lc8 * 8;
            CP_ASYNC_16(sa + row * 144 + lc8 * 16, g);
        }
#pragma unroll
        for (int i = 0; i < 4; ++i) {
            const int row = lrow + i * 32;
            const __half* g = g_Bhi + (((size_t)(n_base + row)) << 9) + k0 + lc8 * 8;
            CP_ASYNC_16(sb + row * 144 + lc8 * 16, g);
        }
        CP_ASYNC_COMMIT();
    };

    const int wid = t >> 5, lane = t & 31;
    const int wm = wid >> 2;
    const int wn = wid & 3;
    const int fr = lane >> 2;
    const int fcb = (lane & 3) * 4;

    const int tile0 = blockIdx.x;
    if (tile0 >= NTILES) return;

    int buf = 0;
    {
        const int m0 = (tile0 & 255) * 128;
        const int n0 = (tile0 >> 8) * 128;
        load_stage(m0, n0, 0, 0);
    }

    for (int tile = tile0; tile < NTILES; tile += GEMM_GRID) {
        const int m_base = (tile & 255) * 128;
        const int n_base = (tile >> 8) * 128;
        const int next_tile = tile + GEMM_GRID;

        float acc[4][4][4];
#pragma unroll
        for (int mi = 0; mi < 4; ++mi)
#pragma unroll
            for (int ni = 0; ni < 4; ++ni)
#pragma unroll
                for (int j = 0; j < 4; ++j) acc[mi][ni][j] = 0.f;

        for (int kc = 0; kc < 8; ++kc) {
            bool has_next;
            if (kc < 7) {
                load_stage(m_base, n_base, kc + 1, buf ^ 1);
                has_next = true;
            } else if (next_tile < NTILES) {
                load_stage((next_tile & 255) * 128, (next_tile >> 8) * 128, 0, buf ^ 1);
                has_next = true;
            } else {
                has_next = false;
            }
            if (has_next) { CP_ASYNC_WAIT(1); } else { CP_ASYNC_WAIT(0); }
            __syncthreads();

            const char* As = smem + buf * STG_BYTES;
            const char* Bs = As + 128 * 144;
#pragma unroll
            for (int kk = 0; kk < 4; ++kk) {
                const int cb = kk * 32 + fcb;
                uint32_t a[4][4];
#pragma unroll
                for (int mi = 0; mi < 4; ++mi) {
                    const int r = wm * 64 + mi * 16 + fr;
                    a[mi][0] = *(const uint32_t*)(As + r * 144 + cb);
                    a[mi][1] = *(const uint32_t*)(As + (r + 8) * 144 + cb);
                    a[mi][2] = *(const uint32_t*)(As + r * 144 + cb + 16);
                    a[mi][3] = *(const uint32_t*)(As + (r + 8) * 144 + cb + 16);
                }
                uint32_t b[4][2];
#pragma unroll
                for (int ni = 0; ni < 4; ++ni) {
                    const int n = wn * 32 + ni * 8 + fr;
                    b[ni][0] = *(const uint32_t*)(Bs + n * 144 + cb);
                    b[ni][1] = *(const uint32_t*)(Bs + n * 144 + cb + 16);
                }
#pragma unroll
                for (int mi = 0; mi < 4; ++mi)
#pragma unroll
                    for (int ni = 0; ni < 4; ++ni)
                        mma_16816_f16(acc[mi][ni], a[mi], b[ni]);
            }
            buf ^= 1;
            __syncthreads();
        }

        // Epilogue (registers -> global; no smem access, safe vs in-flight loads)
#pragma unroll
        for (int mi = 0; mi < 4; ++mi) {
            const int r = m_base + wm * 64 + mi * 16 + fr;
#pragma unroll
            for (int ni = 0; ni < 4; ++ni) {
                const int cg = n_base + wn * 32 + ni * 8 + (lane & 3) * 2;
                *(float2*)(out + (size_t)r * DM_ + cg) =
                    make_float2(acc[mi][ni][0], acc[mi][ni][1]);
                *(float2*)(out + (size_t)(r + 8) * DM_ + cg) =
                    make_float2(acc[mi][ni][2], acc[mi][ni][3]);
            }
        }
    }
}

// ---------------------------------------------------------------------------
extern "C" void kernel_launch(void* const* d_in, const int* in_sizes, int n_in,
                              void* d_out, int out_size) {
    const float* Q     = (const float*)d_in[0];
    const float* V     = (const float*)d_in[1];
    const float* trace = (const float*)d_in[2];
    const float* W     = (const float*)d_in[3];
    float* out = (float*)d_out;

    static bool attr_set = false;
    if (!attr_set) {
        cudaFuncSetAttribute(out_gemm_mma, cudaFuncAttributeMaxDynamicSharedMemorySize, GEMM_SMEM);
        attr_set = true;
    }

    gram_mma<<<dim3(GCH, H_), 256>>>(Q, V);
    reduce_combine<<<dim3(8, H_), 256>>>(trace);
    build_M<<<dim3(12, H_), 256>>>(W);
    out_gemm_mma<<<GEMM_GRID, 256, GEMM_SMEM>>>(out);
}

// round 15
// speedup vs baseline: 1.3024x; 1.3024x over previous
#include <cuda_runtime.h>
#include <cuda_fp16.h>
#include <cstdint>

// Problem constants
#define B_   8
#define H_   8
#define S_   4096
#define D_   64
#define DM_  768
#define SM2  (S_ - 2)            // 4094 (rows entering the Hebbian update)
#define RPB  (S_ - 1)            // 4095 (rows per batch incl. A-only row i=4094)
#define ROWS_A (B_ * RPB)        // 32760
#define DENOM ((float)(B_ * SM2))

#define GCH   32                 // gram chunks
#define GROWS 1024               // rows per chunk

#define MROWS (B_ * S_)          // 32768
#define KDIM  (H_ * D_)          // 512

// ---------------------------------------------------------------------------
// Static device scratch (allocation-free per harness rules)
// ---------------------------------------------------------------------------
__device__ float g_scratch[H_][GCH][2][D_ * D_];
__device__ float g_NT[H_][D_ * D_];
__device__ __align__(16) __half g_Ahi[(size_t)MROWS * KDIM];
__device__ __align__(16) __half g_Bhi[(size_t)DM_ * KDIM];

// ---------------------------------------------------------------------------
// Helpers
// ---------------------------------------------------------------------------
__device__ __forceinline__ uint32_t smem_to_u32(const void* p) {
    uint32_t a;
    asm("{ .reg .u64 t; cvta.to.shared.u64 t, %1; cvt.u32.u64 %0, t; }" : "=r"(a) : "l"(p));
    return a;
}
__device__ __forceinline__ void mma_16816_f16(float* c, const uint32_t* a, const uint32_t* b) {
    asm volatile(
        "mma.sync.aligned.m16n8k16.row.col.f32.f16.f16.f32 "
        "{%0,%1,%2,%3}, {%4,%5,%6,%7}, {%8,%9}, {%0,%1,%2,%3};"
        : "+f"(c[0]), "+f"(c[1]), "+f"(c[2]), "+f"(c[3])
        : "r"(a[0]), "r"(a[1]), "r"(a[2]), "r"(a[3]), "r"(b[0]), "r"(b[1]));
}
__device__ __forceinline__ void ldsm_x4_trans(uint32_t& r0, uint32_t& r1,
                                              uint32_t& r2, uint32_t& r3, uint32_t addr) {
    asm volatile("ldmatrix.sync.aligned.m8n8.x4.trans.shared.b16 {%0,%1,%2,%3}, [%4];"
                 : "=r"(r0), "=r"(r1), "=r"(r2), "=r"(r3) : "r"(addr));
}
#define CP_ASYNC_16(smem_u32, gptr) \
    asm volatile("cp.async.cg.shared.global [%0], [%1], 16;" :: "r"(smem_u32), "l"(gptr))
#define CP_ASYNC_COMMIT() asm volatile("cp.async.commit_group;")
#define CP_ASYNC_WAIT(n)  asm volatile("cp.async.wait_group %0;" :: "n"(n))

// ---------------------------------------------------------------------------
// Kernel 1 (fused): Gram partials via tensor cores + fp16 A write + zeroA.
// EXACT R14 version.
// ---------------------------------------------------------------------------
#define RT 64       // rows per stage
#define RP 72       // padded halfs per smem row

__global__ __launch_bounds__(256, 2) void gram_mma(const float* __restrict__ Q,
                                                   const float* __restrict__ V) {
    const int c = blockIdx.x;   // chunk (1024 rows)
    const int h = blockIdx.y;
    const int t = threadIdx.x;
    const int wid = t >> 5, lane = t & 31;

    // zeroA fusion: block (0,h) zeroes A row b*4096 cols h*64..h*64+63, all b.
    if (c == 0 && t < 64) {
        const int b = t >> 3;       // 0..7
        const int g = t & 7;        // 8-half group
        __half zz[8];
#pragma unroll
        for (int j = 0; j < 8; ++j) zz[j] = __float2half(0.f);
        *(uint4*)(g_Ahi + (((size_t)b * S_) << 9) + h * 64 + g * 8) = *(uint4*)zz;
    }

    __shared__ __half Tqh[RT * RP];   // q_hat, k-major: [r][d]
    __shared__ __half Tq [RT * RP];   // q
    __shared__ __half Tv [RT * RP];   // v (shift+2)

    const uint32_t sTqh = smem_to_u32(Tqh);
    const uint32_t sTq  = smem_to_u32(Tq);
    const uint32_t sTv  = smem_to_u32(Tv);

    const int lr = t >> 2;
    const int tq = t & 3;

    const int p0 = 16 * (wid & 3);
    const uint32_t TA = (wid < 4) ? sTqh : sTq;
    const uint32_t TB = (wid < 4) ? sTqh : sTv;
    const int l8  = lane & 7;
    const int sub = lane >> 3;
    const uint32_t a_off = (uint32_t)((((sub >> 1) * 8 + l8) * RP + p0 + (sub & 1) * 8) * 2);
    const uint32_t b_off = (uint32_t)((((sub & 1) * 8 + l8) * RP + (sub >> 1) * 8) * 2);

    float acc[8][4];
#pragma unroll
    for (int i = 0; i < 8; ++i)
#pragma unroll
        for (int j = 0; j < 4; ++j) acc[i][j] = 0.f;

    for (int st = 0; st < GROWS / RT; ++st) {            // 16 stages
        const int gr = c * GROWS + st * RT + lr;
        float q[16], v[16];
#pragma unroll
        for (int i = 0; i < 16; ++i) { q[i] = 0.f; v[i] = 0.f; }
        const bool valid = (gr < ROWS_A);
        int b = 0, i = 0;
        if (valid) {
            b = gr / RPB;
            i = gr - b * RPB;                            // 0..4094
            const float* qrow = Q + (((size_t)(b * H_ + h)) * S_ + i) * D_ + tq * 16;
#pragma unroll
            for (int j = 0; j < 4; ++j)
                *(float4*)&q[j * 4] = *(const float4*)(qrow + j * 4);
            if (i < SM2) {
                const float* vrow = V + (((size_t)(b * H_ + h)) * S_ + i + 2) * D_ + tq * 16;
#pragma unroll
                for (int j = 0; j < 4; ++j)
                    *(float4*)&v[j * 4] = *(const float4*)(vrow + j * 4);
            }
        }
        // fp16 of raw q — doubles as the A-matrix payload (prepA fusion)
        __half2 hq[8];
#pragma unroll
        for (int j = 0; j < 8; ++j) hq[j] = __floats2half2_rn(q[2 * j], q[2 * j + 1]);
        if (valid) {
            __half* d = g_Ahi + (((size_t)(b * S_ + i + 1)) << 9) + h * 64 + tq * 16;
            *(uint4*)(d)     = *(uint4*)&hq[0];
            *(uint4*)(d + 8) = *(uint4*)&hq[4];
        }
        // mask A-only row (i == 4094) and out-of-range rows out of the MMA
        const bool active = valid && (i < SM2);
        if (!active) {
#pragma unroll
            for (int j = 0; j < 16; ++j) q[j] = 0.f;
#pragma unroll
            for (int j = 0; j < 8; ++j) hq[j] = __halves2half2(__half(0), __half(0));
        }
        // row norm across the 4 lanes covering this row
        float ss = 0.f;
#pragma unroll
        for (int j = 0; j < 16; ++j) ss += q[j] * q[j];
        ss += __shfl_xor_sync(0xffffffffu, ss, 1);
        ss += __shfl_xor_sync(0xffffffffu, ss, 2);
        const float inv = 1.0f / fmaxf(sqrtf(ss), 1e-8f);

        __half2 hqh[8], hv[8];
#pragma unroll
        for (int j = 0; j < 8; ++j) {
            hqh[j] = __floats2half2_rn(q[2 * j] * inv, q[2 * j + 1] * inv);
            hv[j]  = __floats2half2_rn(v[2 * j], v[2 * j + 1]);
        }
        __syncthreads();   // previous stage's mma reads done
        {
            __half* d0 = Tqh + lr * RP + tq * 16;
            *(uint4*)(d0)     = *(uint4*)&hqh[0];
            *(uint4*)(d0 + 8) = *(uint4*)&hqh[4];
            __half* d1 = Tq + lr * RP + tq * 16;
            *(uint4*)(d1)     = *(uint4*)&hq[0];
            *(uint4*)(d1 + 8) = *(uint4*)&hq[4];
            __half* d2 = Tv + lr * RP + tq * 16;
            *(uint4*)(d2)     = *(uint4*)&hv[0];
            *(uint4*)(d2 + 8) = *(uint4*)&hv[4];
        }
        __syncthreads();

#pragma unroll
        for (int ks = 0; ks < RT / 16; ++ks) {           // 4 k16-steps
            const uint32_t kb = (uint32_t)(ks * 16 * RP * 2);
            uint32_t a[4];
            ldsm_x4_trans(a[0], a[1], a[2], a[3], TA + kb + a_off);
#pragma unroll
            for (int nt = 0; nt < 8; nt += 2) {
                uint32_t b0, b1, b2, b3;
                ldsm_x4_trans(b0, b1, b2, b3, TB + kb + b_off + nt * 8 * 2);
                uint32_t bb0[2] = {b0, b1};
                uint32_t bb1[2] = {b2, b3};
                mma_16816_f16(acc[nt],     a, bb0);
                mma_16816_f16(acc[nt + 1], a, bb1);
            }
        }
    }

    // write partials
    float* o = g_scratch[h][c][(wid < 4) ? 0 : 1];
    const int fr = lane >> 2;
    const int c2 = (lane & 3) * 2;
#pragma unroll
    for (int nt = 0; nt < 8; ++nt) {
        const int col = nt * 8 + c2;
        *(float2*)&o[(p0 + fr) * 64 + col]     = make_float2(acc[nt][0], acc[nt][1]);
        *(float2*)&o[(p0 + fr + 8) * 64 + col] = make_float2(acc[nt][2], acc[nt][3]);
    }
}

// ---------------------------------------------------------------------------
// Kernel 2 (fused reduce + combine) — EXACT R13.
// ---------------------------------------------------------------------------
__global__ __launch_bounds__(256) void reduce_combine(const float* __restrict__ trace) {
    const int h  = blockIdx.y;
    const int p0 = blockIdx.x * 8;
    const int t  = threadIdx.x;

    __shared__ float Ts[4096];
    __shared__ float Gs[8 * 64];
    __shared__ float Us[8 * 64];

#pragma unroll
    for (int j = 0; j < 16; ++j)
        Ts[t + 256 * j] = trace[h * 4096 + t + 256 * j];

#pragma unroll
    for (int j = 0; j < 2; ++j) {
        const int e   = t + 256 * j;
        const int idx = p0 * 64 + e;
        float sg = 0.f, su = 0.f;
#pragma unroll 4
        for (int c = 0; c < GCH; ++c) {
            sg += g_scratch[h][c][0][idx];
            su += g_scratch[h][c][1][idx];
        }
        Gs[e] = sg;
        Us[e] = su;
    }
    __syncthreads();

    const float invd = 1.0f / DENOM;
#pragma unroll
    for (int j = 0; j < 2; ++j) {
        const int e  = t + 256 * j;
        const int pl = e >> 6, q = e & 63;
        float acc = 0.f;
#pragma unroll 8
        for (int k = 0; k < 64; ++k)
            acc += Gs[pl * 64 + k] * Ts[k * 64 + q];
        g_NT[h][(p0 + pl) * 64 + q] =
            0.99f * (Ts[(p0 + pl) * 64 + q] - acc * invd) + 0.1f * Us[e] * invd;
    }
}

// ---------------------------------------------------------------------------
// Kernel 3: B[n][h*64+p] = sum_q NT[h][p][q] * W[n][h*64+q] -> fp16. EXACT R13.
// ---------------------------------------------------------------------------
__global__ __launch_bounds__(256) void build_M(const float* __restrict__ W) {
    const int h  = blockIdx.y;
    const int n0 = blockIdx.x * 64;
    const int t  = threadIdx.x;
    __shared__ float Wq[64][72];   // [q][n]
    __shared__ float Nq[64][72];   // [q][p]
#pragma unroll
    for (int j = 0; j < 4; ++j) {
        const int idx = t + j * 256;
        const int row = idx >> 4;
        const int q4  = (idx & 15) * 4;
        float4 wv = *(const float4*)(W + (size_t)(n0 + row) * KDIM + h * 64 + q4);
        Wq[q4 + 0][row] = wv.x; Wq[q4 + 1][row] = wv.y;
        Wq[q4 + 2][row] = wv.z; Wq[q4 + 3][row] = wv.w;
        float4 nv = *(const float4*)(&g_NT[h][row * 64 + q4]);
        Nq[q4 + 0][row] = nv.x; Nq[q4 + 1][row] = nv.y;
        Nq[q4 + 2][row] = nv.z; Nq[q4 + 3][row] = nv.w;
    }
    __syncthreads();
    const int tx = t & 15;     // p block
    const int ty = t >> 4;     // n block
    float acc[4][4];
#pragma unroll
    for (int i = 0; i < 4; ++i)
#pragma unroll
        for (int j = 0; j < 4; ++j) acc[i][j] = 0.f;
#pragma unroll 8
    for (int q = 0; q < 64; ++q) {
        const float4 wv = *(const float4*)&Wq[q][ty * 4];
        const float4 nv = *(const float4*)&Nq[q][tx * 4];
        const float w[4] = {wv.x, wv.y, wv.z, wv.w};
        const float nn[4] = {nv.x, nv.y, nv.z, nv.w};
#pragma unroll
        for (int i = 0; i < 4; ++i)
#pragma unroll
            for (int j = 0; j < 4; ++j)
                acc[i][j] += w[i] * nn[j];
    }
#pragma unroll
    for (int i = 0; i < 4; ++i) {
        const int n = n0 + ty * 4 + i;
#pragma unroll
        for (int j = 0; j < 4; ++j) {
            const int k = h * 64 + tx * 4 + j;
            g_Bhi[(size_t)n * KDIM + k] = __float2half_rn(acc[i][j]);
        }
    }
}

// ---------------------------------------------------------------------------
// Kernel 4: out = Ahi @ Bhi^T — one tile per CTA (no persistence, no spills),
// BM=128, BN=64 (grid 12x256 = 3072 CTAs) to shrink wave-tail idle.
// K-order per output element identical to R13 -> bit-identical result.
// 8 warps as 2(m) x 4(n): warp tile 64m x 16n, acc[4][2][4].
// ---------------------------------------------------------------------------
#define STG_BYTES 27648                         // (128*72 + 64*72) * 2B
#define GEMM_SMEM (2 * STG_BYTES)               // 55296

__global__ __launch_bounds__(256, 2) void out_gemm_mma(float* __restrict__ out) {
    extern __shared__ __align__(16) char smem[];
    const int t = threadIdx.x;
    const int n_base = blockIdx.x * 64;
    const int m_base = blockIdx.y * 128;
    const uint32_t sbase = smem_to_u32(smem);

    const int lrow = t >> 3;        // 0..31
    const int lc8  = t & 7;         // 16B chunk within 64-col row

    auto load_stage = [&](int kc, int stage) {
        const int k0 = kc * 64;
        const uint32_t sa = sbase + stage * STG_BYTES;
        const uint32_t sb = sa + 128 * 144;
#pragma unroll
        for (int i = 0; i < 4; ++i) {
            const int row = lrow + i * 32;
            const __half* g = g_Ahi + (((size_t)(m_base + row)) << 9) + k0 + lc8 * 8;
            CP_ASYNC_16(sa + row * 144 + lc8 * 16, g);
        }
#pragma unroll
        for (int i = 0; i < 2; ++i) {
            const int row = lrow + i * 32;          // 0..63
            const __half* g = g_Bhi + (((size_t)(n_base + row)) << 9) + k0 + lc8 * 8;
            CP_ASYNC_16(sb + row * 144 + lc8 * 16, g);
        }
        CP_ASYNC_COMMIT();
    };

    const int wid = t >> 5, lane = t & 31;
    const int wm = wid >> 2;        // 0..1  (64 m-rows each)
    const int wn = wid & 3;         // 0..3  (16 n-cols each)
    const int fr = lane >> 2;       // 0..7
    const int fcb = (lane & 3) * 4; // k byte offset (2 fp16)

    float acc[4][2][4];
#pragma unroll
    for (int mi = 0; mi < 4; ++mi)
#pragma unroll
        for (int ni = 0; ni < 2; ++ni)
#pragma unroll
            for (int j = 0; j < 4; ++j) acc[mi][ni][j] = 0.f;

    load_stage(0, 0);
    for (int kc = 0; kc < 8; ++kc) {
        if (kc + 1 < 8) {
            load_stage(kc + 1, (kc + 1) & 1);
            CP_ASYNC_WAIT(1);
        } else {
            CP_ASYNC_WAIT(0);
        }
        __syncthreads();

        const char* As = smem + (kc & 1) * STG_BYTES;
        const char* Bs = As + 128 * 144;
#pragma unroll
        for (int kk = 0; kk < 4; ++kk) {
            const int cb = kk * 32 + fcb;        // k16-step byte offset
            uint32_t a[4][4];
#pragma unroll
            for (int mi = 0; mi < 4; ++mi) {
                const int r = wm * 64 + mi * 16 + fr;
                a[mi][0] = *(const uint32_t*)(As + r * 144 + cb);
                a[mi][1] = *(const uint32_t*)(As + (r + 8) * 144 + cb);
                a[mi][2] = *(const uint32_t*)(As + r * 144 + cb + 16);
                a[mi][3] = *(const uint32_t*)(As + (r + 8) * 144 + cb + 16);
            }
            uint32_t b[2][2];
#pragma unroll
            for (int ni = 0; ni < 2; ++ni) {
                const int n = wn * 16 + ni * 8 + fr;
                b[ni][0] = *(const uint32_t*)(Bs + n * 144 + cb);
                b[ni][1] = *(const uint32_t*)(Bs + n * 144 + cb + 16);
            }
#pragma unroll
            for (int mi = 0; mi < 4; ++mi)
#pragma unroll
                for (int ni = 0; ni < 2; ++ni)
                    mma_16816_f16(acc[mi][ni], a[mi], b[ni]);
        }
        __syncthreads();
    }

    // Epilogue: c0,c1 -> (r, cg..cg+1); c2,c3 -> (r+8, cg..cg+1)
#pragma unroll
    for (int mi = 0; mi < 4; ++mi) {
        const int r = m_base + wm * 64 + mi * 16 + fr;
#pragma unroll
        for (int ni = 0; ni < 2; ++ni) {
            const int cg = n_base + wn * 16 + ni * 8 + (lane & 3) * 2;
            *(float2*)(out + (size_t)r * DM_ + cg) =
                make_float2(acc[mi][ni][0], acc[mi][ni][1]);
            *(float2*)(out + (size_t)(r + 8) * DM_ + cg) =
                make_float2(acc[mi][ni][2], acc[mi][ni][3]);
        }
    }
}

// ---------------------------------------------------------------------------
extern "C" void kernel_launch(void* const* d_in, const int* in_sizes, int n_in,
                              void* d_out, int out_size) {
    const float* Q     = (const float*)d_in[0];
    const float* V     = (const float*)d_in[1];
    const float* trace = (const float*)d_in[2];
    const float* W     = (const float*)d_in[3];
    float* out = (float*)d_out;

    static bool attr_set = false;
    if (!attr_set) {
        cudaFuncSetAttribute(out_gemm_mma, cudaFuncAttributeMaxDynamicSharedMemorySize, GEMM_SMEM);
        attr_set = true;
    }

    gram_mma<<<dim3(GCH, H_), 256>>>(Q, V);
    reduce_combine<<<dim3(8, H_), 256>>>(trace);
    build_M<<<dim3(12, H_), 256>>>(W);
    out_gemm_mma<<<dim3(DM_ / 64, MROWS / 128), 256, GEMM_SMEM>>>(out);
}

// round 17
// speedup vs baseline: 1.5966x; 1.2259x over previous
#include <cuda_runtime.h>
#include <cuda_fp16.h>
#include <cstdint>

// Problem constants
#define B_   8
#define H_   8
#define S_   4096
#define D_   64
#define DM_  768
#define SM2  (S_ - 2)            // 4094 (rows entering the Hebbian update)
#define RPB  (S_ - 1)            // 4095 (rows per batch incl. A-only row i=4094)
#define ROWS_A (B_ * RPB)        // 32760
#define DENOM ((float)(B_ * SM2))

#define GCH   32                 // gram chunks
#define GROWS 1024               // rows per chunk

#define MROWS (B_ * S_)          // 32768
#define KDIM  (H_ * D_)          // 512

// ---------------------------------------------------------------------------
// Static device scratch (allocation-free per harness rules)
// ---------------------------------------------------------------------------
__device__ float g_scratch[H_][GCH][2][D_ * D_];
__device__ float g_NT[H_][D_ * D_];
__device__ __align__(16) __half g_Ahi[(size_t)MROWS * KDIM];
__device__ __align__(16) __half g_Bhi[(size_t)DM_ * KDIM];

// ---------------------------------------------------------------------------
// Helpers
// ---------------------------------------------------------------------------
__device__ __forceinline__ uint32_t smem_to_u32(const void* p) {
    uint32_t a;
    asm("{ .reg .u64 t; cvta.to.shared.u64 t, %1; cvt.u32.u64 %0, t; }" : "=r"(a) : "l"(p));
    return a;
}
__device__ __forceinline__ void mma_16816_f16(float* c, const uint32_t* a, const uint32_t* b) {
    asm volatile(
        "mma.sync.aligned.m16n8k16.row.col.f32.f16.f16.f32 "
        "{%0,%1,%2,%3}, {%4,%5,%6,%7}, {%8,%9}, {%0,%1,%2,%3};"
        : "+f"(c[0]), "+f"(c[1]), "+f"(c[2]), "+f"(c[3])
        : "r"(a[0]), "r"(a[1]), "r"(a[2]), "r"(a[3]), "r"(b[0]), "r"(b[1]));
}
__device__ __forceinline__ void ldsm_x4_trans(uint32_t& r0, uint32_t& r1,
                                              uint32_t& r2, uint32_t& r3, uint32_t addr) {
    asm volatile("ldmatrix.sync.aligned.m8n8.x4.trans.shared.b16 {%0,%1,%2,%3}, [%4];"
                 : "=r"(r0), "=r"(r1), "=r"(r2), "=r"(r3) : "r"(addr));
}
__device__ __forceinline__ void ldsm_x4(uint32_t& r0, uint32_t& r1,
                                        uint32_t& r2, uint32_t& r3, uint32_t addr) {
    asm volatile("ldmatrix.sync.aligned.m8n8.x4.shared.b16 {%0,%1,%2,%3}, [%4];"
                 : "=r"(r0), "=r"(r1), "=r"(r2), "=r"(r3) : "r"(addr));
}
#define CP_ASYNC_16(smem_u32, gptr) \
    asm volatile("cp.async.cg.shared.global [%0], [%1], 16;" :: "r"(smem_u32), "l"(gptr))
#define CP_ASYNC_COMMIT() asm volatile("cp.async.commit_group;")
#define CP_ASYNC_WAIT(n)  asm volatile("cp.async.wait_group %0;" :: "n"(n))

// ---------------------------------------------------------------------------
// Kernel 1 (fused): Gram partials via tensor cores + fp16 A write + zeroA.
// EXACT R14/R15 version.
// ---------------------------------------------------------------------------
#define RT 64       // rows per stage
#define RP 72       // padded halfs per smem row

__global__ __launch_bounds__(256, 2) void gram_mma(const float* __restrict__ Q,
                                                   const float* __restrict__ V) {
    const int c = blockIdx.x;   // chunk (1024 rows)
    const int h = blockIdx.y;
    const int t = threadIdx.x;
    const int wid = t >> 5, lane = t & 31;

    // zeroA fusion: block (0,h) zeroes A row b*4096 cols h*64..h*64+63, all b.
    if (c == 0 && t < 64) {
        const int b = t >> 3;       // 0..7
        const int g = t & 7;        // 8-half group
        __half zz[8];
#pragma unroll
        for (int j = 0; j < 8; ++j) zz[j] = __float2half(0.f);
        *(uint4*)(g_Ahi + (((size_t)b * S_) << 9) + h * 64 + g * 8) = *(uint4*)zz;
    }

    __shared__ __half Tqh[RT * RP];   // q_hat, k-major: [r][d]
    __shared__ __half Tq [RT * RP];   // q
    __shared__ __half Tv [RT * RP];   // v (shift+2)

    const uint32_t sTqh = smem_to_u32(Tqh);
    const uint32_t sTq  = smem_to_u32(Tq);
    const uint32_t sTv  = smem_to_u32(Tv);

    const int lr = t >> 2;
    const int tq = t & 3;

    const int p0 = 16 * (wid & 3);
    const uint32_t TA = (wid < 4) ? sTqh : sTq;
    const uint32_t TB = (wid < 4) ? sTqh : sTv;
    const int l8  = lane & 7;
    const int sub = lane >> 3;
    const uint32_t a_off = (uint32_t)((((sub >> 1) * 8 + l8) * RP + p0 + (sub & 1) * 8) * 2);
    const uint32_t b_off = (uint32_t)((((sub & 1) * 8 + l8) * RP + (sub >> 1) * 8) * 2);

    float acc[8][4];
#pragma unroll
    for (int i = 0; i < 8; ++i)
#pragma unroll
        for (int j = 0; j < 4; ++j) acc[i][j] = 0.f;

    for (int st = 0; st < GROWS / RT; ++st) {            // 16 stages
        const int gr = c * GROWS + st * RT + lr;
        float q[16], v[16];
#pragma unroll
        for (int i = 0; i < 16; ++i) { q[i] = 0.f; v[i] = 0.f; }
        const bool valid = (gr < ROWS_A);
        int b = 0, i = 0;
        if (valid) {
            b = gr / RPB;
            i = gr - b * RPB;                            // 0..4094
            const float* qrow = Q + (((size_t)(b * H_ + h)) * S_ + i) * D_ + tq * 16;
#pragma unroll
            for (int j = 0; j < 4; ++j)
                *(float4*)&q[j * 4] = *(const float4*)(qrow + j * 4);
            if (i < SM2) {
                const float* vrow = V + (((size_t)(b * H_ + h)) * S_ + i + 2) * D_ + tq * 16;
#pragma unroll
                for (int j = 0; j < 4; ++j)
                    *(float4*)&v[j * 4] = *(const float4*)(vrow + j * 4);
            }
        }
        // fp16 of raw q — doubles as the A-matrix payload (prepA fusion)
        __half2 hq[8];
#pragma unroll
        for (int j = 0; j < 8; ++j) hq[j] = __floats2half2_rn(q[2 * j], q[2 * j + 1]);
        if (valid) {
            __half* d = g_Ahi + (((size_t)(b * S_ + i + 1)) << 9) + h * 64 + tq * 16;
            *(uint4*)(d)     = *(uint4*)&hq[0];
            *(uint4*)(d + 8) = *(uint4*)&hq[4];
        }
        // mask A-only row (i == 4094) and out-of-range rows out of the MMA
        const bool active = valid && (i < SM2);
        if (!active) {
#pragma unroll
            for (int j = 0; j < 16; ++j) q[j] = 0.f;
#pragma unroll
            for (int j = 0; j < 8; ++j) hq[j] = __halves2half2(__half(0), __half(0));
        }
        // row norm across the 4 lanes covering this row
        float ss = 0.f;
#pragma unroll
        for (int j = 0; j < 16; ++j) ss += q[j] * q[j];
        ss += __shfl_xor_sync(0xffffffffu, ss, 1);
        ss += __shfl_xor_sync(0xffffffffu, ss, 2);
        const float inv = 1.0f / fmaxf(sqrtf(ss), 1e-8f);

        __half2 hqh[8], hv[8];
#pragma unroll
        for (int j = 0; j < 8; ++j) {
            hqh[j] = __floats2half2_rn(q[2 * j] * inv, q[2 * j + 1] * inv);
            hv[j]  = __floats2half2_rn(v[2 * j], v[2 * j + 1]);
        }
        __syncthreads();   // previous stage's mma reads done
        {
            __half* d0 = Tqh + lr * RP + tq * 16;
            *(uint4*)(d0)     = *(uint4*)&hqh[0];
            *(uint4*)(d0 + 8) = *(uint4*)&hqh[4];
            __half* d1 = Tq + lr * RP + tq * 16;
            *(uint4*)(d1)     = *(uint4*)&hq[0];
            *(uint4*)(d1 + 8) = *(uint4*)&hq[4];
            __half* d2 = Tv + lr * RP + tq * 16;
            *(uint4*)(d2)     = *(uint4*)&hv[0];
            *(uint4*)(d2 + 8) = *(uint4*)&hv[4];
        }
        __syncthreads();

#pragma unroll
        for (int ks = 0; ks < RT / 16; ++ks) {           // 4 k16-steps
            const uint32_t kb = (uint32_t)(ks * 16 * RP * 2);
            uint32_t a[4];
            ldsm_x4_trans(a[0], a[1], a[2], a[3], TA + kb + a_off);
#pragma unroll
            for (int nt = 0; nt < 8; nt += 2) {
                uint32_t b0, b1, b2, b3;
                ldsm_x4_trans(b0, b1, b2, b3, TB + kb + b_off + nt * 8 * 2);
                uint32_t bb0[2] = {b0, b1};
                uint32_t bb1[2] = {b2, b3};
                mma_16816_f16(acc[nt],     a, bb0);
                mma_16816_f16(acc[nt + 1], a, bb1);
            }
        }
    }

    // write partials
    float* o = g_scratch[h][c][(wid < 4) ? 0 : 1];
    const int fr = lane >> 2;
    const int c2 = (lane & 3) * 2;
#pragma unroll
    for (int nt = 0; nt < 8; ++nt) {
        const int col = nt * 8 + c2;
        *(float2*)&o[(p0 + fr) * 64 + col]     = make_float2(acc[nt][0], acc[nt][1]);
        *(float2*)&o[(p0 + fr + 8) * 64 + col] = make_float2(acc[nt][2], acc[nt][3]);
    }
}

// ---------------------------------------------------------------------------
// Kernel 2 (fused reduce + combine) — EXACT R13.
// ---------------------------------------------------------------------------
__global__ __launch_bounds__(256) void reduce_combine(const float* __restrict__ trace) {
    const int h  = blockIdx.y;
    const int p0 = blockIdx.x * 8;
    const int t  = threadIdx.x;

    __shared__ float Ts[4096];
    __shared__ float Gs[8 * 64];
    __shared__ float Us[8 * 64];

#pragma unroll
    for (int j = 0; j < 16; ++j)
        Ts[t + 256 * j] = trace[h * 4096 + t + 256 * j];

#pragma unroll
    for (int j = 0; j < 2; ++j) {
        const int e   = t + 256 * j;
        const int idx = p0 * 64 + e;
        float sg = 0.f, su = 0.f;
#pragma unroll 4
        for (int c = 0; c < GCH; ++c) {
            sg += g_scratch[h][c][0][idx];
            su += g_scratch[h][c][1][idx];
        }
        Gs[e] = sg;
        Us[e] = su;
    }
    __syncthreads();

    const float invd = 1.0f / DENOM;
#pragma unroll
    for (int j = 0; j < 2; ++j) {
        const int e  = t + 256 * j;
        const int pl = e >> 6, q = e & 63;
        float acc = 0.f;
#pragma unroll 8
        for (int k = 0; k < 64; ++k)
            acc += Gs[pl * 64 + k] * Ts[k * 64 + q];
        g_NT[h][(p0 + pl) * 64 + q] =
            0.99f * (Ts[(p0 + pl) * 64 + q] - acc * invd) + 0.1f * Us[e] * invd;
    }
}

// ---------------------------------------------------------------------------
// Kernel 3: B[n][h*64+p] = sum_q NT[h][p][q] * W[n][h*64+q] -> fp16. EXACT R13.
// ---------------------------------------------------------------------------
__global__ __launch_bounds__(256) void build_M(const float* __restrict__ W) {
    const int h  = blockIdx.y;
    const int n0 = blockIdx.x * 64;
    const int t  = threadIdx.x;
    __shared__ float Wq[64][72];   // [q][n]
    __shared__ float Nq[64][72];   // [q][p]
#pragma unroll
    for (int j = 0; j < 4; ++j) {
        const int idx = t + j * 256;
        const int row = idx >> 4;
        const int q4  = (idx & 15) * 4;
        float4 wv = *(const float4*)(W + (size_t)(n0 + row) * KDIM + h * 64 + q4);
        Wq[q4 + 0][row] = wv.x; Wq[q4 + 1][row] = wv.y;
        Wq[q4 + 2][row] = wv.z; Wq[q4 + 3][row] = wv.w;
        float4 nv = *(const float4*)(&g_NT[h][row * 64 + q4]);
        Nq[q4 + 0][row] = nv.x; Nq[q4 + 1][row] = nv.y;
        Nq[q4 + 2][row] = nv.z; Nq[q4 + 3][row] = nv.w;
    }
    __syncthreads();
    const int tx = t & 15;     // p block
    const int ty = t >> 4;     // n block
    float acc[4][4];
#pragma unroll
    for (int i = 0; i < 4; ++i)
#pragma unroll
        for (int j = 0; j < 4; ++j) acc[i][j] = 0.f;
#pragma unroll 8
    for (int q = 0; q < 64; ++q) {
        const float4 wv = *(const float4*)&Wq[q][ty * 4];
        const float4 nv = *(const float4*)&Nq[q][tx * 4];
        const float w[4] = {wv.x, wv.y, wv.z, wv.w};
        const float nn[4] = {nv.x, nv.y, nv.z, nv.w};
#pragma unroll
        for (int i = 0; i < 4; ++i)
#pragma unroll
            for (int j = 0; j < 4; ++j)
                acc[i][j] += w[i] * nn[j];
    }
#pragma unroll
    for (int i = 0; i < 4; ++i) {
        const int n = n0 + ty * 4 + i;
#pragma unroll
        for (int j = 0; j < 4; ++j) {
            const int k = h * 64 + tx * 4 + j;
            g_Bhi[(size_t)n * KDIM + k] = __float2half_rn(acc[i][j]);
        }
    }
}

// ---------------------------------------------------------------------------
// Kernel 4: out = Ahi @ Bhi^T — R13 shape (BM=BN=128, one tile/CTA, grid
// (6,256)) with fragment loads via ldmatrix (6 LDSM per kk vs 24 LDS).
// Register values identical to R13's scalar loads -> bit-identical output.
// ---------------------------------------------------------------------------
#define STG_BYTES 36864                         // (128*72 + 128*72) * 2B
#define GEMM_SMEM (2 * STG_BYTES)               // 73728

__global__ __launch_bounds__(256, 2) void out_gemm_mma(float* __restrict__ out) {
    extern __shared__ __align__(16) char smem[];
    const int t = threadIdx.x;
    const int n_base = blockIdx.x * 128;
    const int m_base = blockIdx.y * 128;
    const uint32_t sbase = smem_to_u32(smem);

    const int lrow = t >> 3;
    const int lc8  = t & 7;

    auto load_stage = [&](int kc, int stage) {
        const int k0 = kc * 64;
        const uint32_t sa = sbase + stage * STG_BYTES;
        const uint32_t sb = sa + 128 * 144;
#pragma unroll
        for (int i = 0; i < 4; ++i) {
            const int row = lrow + i * 32;
            const __half* g = g_Ahi + (((size_t)(m_base + row)) << 9) + k0 + lc8 * 8;
            CP_ASYNC_16(sa + row * 144 + lc8 * 16, g);
        }
#pragma unroll
        for (int i = 0; i < 4; ++i) {
            const int row = lrow + i * 32;
            const __half* g = g_Bhi + (((size_t)(n_base + row)) << 9) + k0 + lc8 * 8;
            CP_ASYNC_16(sb + row * 144 + lc8 * 16, g);
        }
        CP_ASYNC_COMMIT();
    };

    const int wid = t >> 5, lane = t & 31;
    const int wm = wid >> 2;        // 0..1  (64 m-rows)
    const int wn = wid & 3;         // 0..3  (32 n-cols)
    const int fr = lane >> 2;       // 0..7

    // ldmatrix per-thread fragment offsets (byte offsets within tile):
    //  A (x4 per mi): matrices [rows, k0][rows+8, k0][rows, k0+8][rows+8, k0+8]
    //    lane -> row = wm*64 + (lane&15), col-half = lane>>4
    const uint32_t a_frag = (uint32_t)((wm * 64 + (lane & 15)) * 144 + (lane >> 4) * 16);
    //  B (x4 covering ni pair): [nA, k0][nA, k0+8][nA+8, k0][nA+8, k0+8]
    //    lane -> row = wn*32 + ((lane>>4)<<3) + (lane&7), col-half = (lane>>3)&1
    const uint32_t b_frag = (uint32_t)((wn * 32 + ((lane >> 4) << 3) + (lane & 7)) * 144
                                       + ((lane >> 3) & 1) * 16);

    float acc[4][4][4];
#pragma unroll
    for (int mi = 0; mi < 4; ++mi)
#pragma unroll
        for (int ni = 0; ni < 4; ++ni)
#pragma unroll
            for (int j = 0; j < 4; ++j) acc[mi][ni][j] = 0.f;

    load_stage(0, 0);
    for (int kc = 0; kc < 8; ++kc) {
        if (kc + 1 < 8) {
            load_stage(kc + 1, (kc + 1) & 1);
            CP_ASYNC_WAIT(1);
        } else {
            CP_ASYNC_WAIT(0);
        }
        __syncthreads();

        const uint32_t As_u = sbase + (kc & 1) * STG_BYTES;
        const uint32_t Bs_u = As_u + 128 * 144;
#pragma unroll
        for (int kk = 0; kk < 4; ++kk) {
            const uint32_t kb = kk * 32;
            uint32_t a[4][4];
#pragma unroll
            for (int mi = 0; mi < 4; ++mi)
                ldsm_x4(a[mi][0], a[mi][1], a[mi][2], a[mi][3],
                        As_u + a_frag + mi * (16 * 144) + kb);
            uint32_t b[4][2];
            ldsm_x4(b[0][0], b[0][1], b[1][0], b[1][1], Bs_u + b_frag + kb);
            ldsm_x4(b[2][0], b[2][1], b[3][0], b[3][1], Bs_u + b_frag + 16 * 144 + kb);
#pragma unroll
            for (int mi = 0; mi < 4; ++mi)
#pragma unroll
                for (int ni = 0; ni < 4; ++ni)
                    mma_16816_f16(acc[mi][ni], a[mi], b[ni]);
        }
        __syncthreads();
    }

    // Epilogue: c0,c1 -> (r, cg..cg+1); c2,c3 -> (r+8, cg..cg+1)
#pragma unroll
    for (int mi = 0; mi < 4; ++mi) {
        const int r = m_base + wm * 64 + mi * 16 + fr;
#pragma unroll
        for (int ni = 0; ni < 4; ++ni) {
            const int cg = n_base + wn * 32 + ni * 8 + (lane & 3) * 2;
            *(float2*)(out + (size_t)r * DM_ + cg) =
                make_float2(acc[mi][ni][0], acc[mi][ni][1]);
            *(float2*)(out + (size_t)(r + 8) * DM_ + cg) =
                make_float2(acc[mi][ni][2], acc[mi][ni][3]);
        }
    }
}

// ---------------------------------------------------------------------------
extern "C" void kernel_launch(void* const* d_in, const int* in_sizes, int n_in,
                              void* d_out, int out_size) {
    const float* Q     = (const float*)d_in[0];
    const float* V     = (const float*)d_in[1];
    const float* trace = (const float*)d_in[2];
    const float* W     = (const float*)d_in[3];
    float* out = (float*)d_out;

    static bool attr_set = false;
    if (!attr_set) {
        cudaFuncSetAttribute(out_gemm_mma, cudaFuncAttributeMaxDynamicSharedMemorySize, GEMM_SMEM);
        attr_set = true;
    }

    gram_mma<<<dim3(GCH, H_), 256>>>(Q, V);
    reduce_combine<<<dim3(8, H_), 256>>>(trace);
    build_M<<<dim3(12, H_), 256>>>(W);
    out_gemm_mma<<<dim3(DM_ / 128, MROWS / 128), 256, GEMM_SMEM>>>(out);
}